// round 14
// baseline (speedup 1.0000x reference)
#include <cuda_runtime.h>
#include <cstdint>

#define NN 50000
#define NE 25000
#define CC 128
#define ESTRIDE 96   // slots per edge bucket (mean deg 24, sigma ~4.9)
#define NSTRIDE 64   // slots per node bucket (mean deg 12, sigma ~3.5)

// ---- scratch (device globals; no allocation) ----
__device__ __align__(16) float g_emean[NE * CC];  // per-edge mean of gathered x
__device__ __align__(16) float g_e2[NE * CC];     // (relu(mean@W1^T+b1))@W2^T + b2
__device__ int g_cc_e[NE];              // per-edge degree (atomic cursor)
__device__ int g_cc_n[NN];              // per-node degree (atomic cursor)
__device__ int g_lst_e[NE * ESTRIDE];   // node ids bucketed by edge
__device__ int g_lst_n[NN * NSTRIDE];   // edge ids bucketed by node

// ---- prep: zero degree counters ----
__global__ void prep_kernel() {
    int tid = blockIdx.x * blockDim.x + threadIdx.x;
    int stride = gridDim.x * blockDim.x;
    for (int i = tid; i < NE; i += stride) g_cc_e[i] = 0;
    for (int i = tid; i < NN; i += stride) g_cc_n[i] = 0;
}

// ---- fill: one pass, 4 incidences per thread, fixed-stride buckets ----
__global__ void fill_kernel(const int* __restrict__ nidx,
                            const int* __restrict__ eidx, int ninc) {
    int base = (blockIdx.x * blockDim.x + threadIdx.x) * 4;
    if (base >= ninc) return;
    int cnt = min(4, ninc - base);
    int n[4], e[4];
#pragma unroll
    for (int q = 0; q < 4; q++) {
        int i = (q < cnt) ? base + q : base;
        n[q] = __ldg(nidx + i);
        e[q] = __ldg(eidx + i);
    }
    int p[4], r[4];
#pragma unroll
    for (int q = 0; q < 4; q++) {
        if (q < cnt) {
            p[q] = atomicAdd(&g_cc_e[e[q]], 1);
            r[q] = atomicAdd(&g_cc_n[n[q]], 1);
        }
    }
#pragma unroll
    for (int q = 0; q < 4; q++) {
        if (q < cnt) {
            if (p[q] < ESTRIDE) g_lst_e[e[q] * ESTRIDE + p[q]] = n[q];
            if (r[q] < NSTRIDE) g_lst_n[n[q] * NSTRIDE + r[q]] = e[q];
        }
    }
}

// ---- gather1: g_emean[e] = mean of x[n] over incident nodes ----
__global__ void gather1_kernel(const float* __restrict__ x) {
    int gw = (blockIdx.x * blockDim.x + threadIdx.x) >> 5;
    int lane = threadIdx.x & 31;
    if (gw >= NE) return;
    const int* lst = g_lst_e + gw * ESTRIDE;
    int deg = min(__ldg(g_cc_e + gw), ESTRIDE);
    float4 acc = make_float4(0.f, 0.f, 0.f, 0.f);
    int j = 0;
    for (; j + 4 <= deg; j += 4) {
        int n0 = __ldg(lst + j);
        int n1 = __ldg(lst + j + 1);
        int n2 = __ldg(lst + j + 2);
        int n3 = __ldg(lst + j + 3);
        float4 v0 = *reinterpret_cast<const float4*>(x + (size_t)n0 * CC + lane * 4);
        float4 v1 = *reinterpret_cast<const float4*>(x + (size_t)n1 * CC + lane * 4);
        float4 v2 = *reinterpret_cast<const float4*>(x + (size_t)n2 * CC + lane * 4);
        float4 v3 = *reinterpret_cast<const float4*>(x + (size_t)n3 * CC + lane * 4);
        acc.x += v0.x + v1.x + v2.x + v3.x;
        acc.y += v0.y + v1.y + v2.y + v3.y;
        acc.z += v0.z + v1.z + v2.z + v3.z;
        acc.w += v0.w + v1.w + v2.w + v3.w;
    }
    for (; j < deg; j++) {
        int n0 = __ldg(lst + j);
        float4 v0 = *reinterpret_cast<const float4*>(x + (size_t)n0 * CC + lane * 4);
        acc.x += v0.x; acc.y += v0.y; acc.z += v0.z; acc.w += v0.w;
    }
    float s = 1.f / (float)max(deg, 1);
    acc.x *= s; acc.y *= s; acc.z *= s; acc.w *= s;
    *reinterpret_cast<float4*>(g_emean + (size_t)gw * CC + lane * 4) = acc;
}

// ---- gather2: out[n] = relu(mean of g_e2[e] over incident edges) ----
__global__ void gather2_kernel(float* __restrict__ out) {
    int gw = (blockIdx.x * blockDim.x + threadIdx.x) >> 5;
    int lane = threadIdx.x & 31;
    if (gw >= NN) return;
    const int* lst = g_lst_n + gw * NSTRIDE;
    int deg = min(__ldg(g_cc_n + gw), NSTRIDE);
    float4 acc = make_float4(0.f, 0.f, 0.f, 0.f);
    int j = 0;
    for (; j + 4 <= deg; j += 4) {
        int e0 = __ldg(lst + j);
        int e1 = __ldg(lst + j + 1);
        int e2i = __ldg(lst + j + 2);
        int e3 = __ldg(lst + j + 3);
        float4 v0 = *reinterpret_cast<const float4*>(g_e2 + (size_t)e0 * CC + lane * 4);
        float4 v1 = *reinterpret_cast<const float4*>(g_e2 + (size_t)e1 * CC + lane * 4);
        float4 v2 = *reinterpret_cast<const float4*>(g_e2 + (size_t)e2i * CC + lane * 4);
        float4 v3 = *reinterpret_cast<const float4*>(g_e2 + (size_t)e3 * CC + lane * 4);
        acc.x += v0.x + v1.x + v2.x + v3.x;
        acc.y += v0.y + v1.y + v2.y + v3.y;
        acc.z += v0.z + v1.z + v2.z + v3.z;
        acc.w += v0.w + v1.w + v2.w + v3.w;
    }
    for (; j < deg; j++) {
        int e0 = __ldg(lst + j);
        float4 v0 = *reinterpret_cast<const float4*>(g_e2 + (size_t)e0 * CC + lane * 4);
        acc.x += v0.x; acc.y += v0.y; acc.z += v0.z; acc.w += v0.w;
    }
    float s = 1.f / (float)max(deg, 1);
    acc.x = fmaxf(acc.x * s, 0.f);
    acc.y = fmaxf(acc.y * s, 0.f);
    acc.z = fmaxf(acc.z * s, 0.f);
    acc.w = fmaxf(acc.w * s, 0.f);
    *reinterpret_cast<float4*>(out + (size_t)gw * CC + lane * 4) = acc;
}

__device__ __forceinline__ uint32_t f2tf32(float f) {
    uint32_t u;
    asm("cvt.rna.tf32.f32 %0, %1;" : "=r"(u) : "f"(f));
    return u;
}

// ---- fused double tf32 GEMM per 64-row tile ----
// Stage A: T = relu( g_emean @ W1^T + b1 )  [64x128], kept in smem (tf32)
// Stage B: e2 = T @ W2^T + b2               [64x128], written to gmem
__global__ void __launch_bounds__(256) fused_gemm(const float* __restrict__ W1,
                                                  const float* __restrict__ b1,
                                                  const float* __restrict__ W2,
                                                  const float* __restrict__ b2) {
    extern __shared__ uint32_t smem[];
    uint32_t (*Ts)[132] = reinterpret_cast<uint32_t(*)[132]>(smem);
    uint32_t (*Bs)[36]  = reinterpret_cast<uint32_t(*)[36]>(smem + 64 * 132);
    uint32_t (*As)[36]  = reinterpret_cast<uint32_t(*)[36]>(smem + 64 * 132 + 128 * 36);

    const int M = NE;
    const int tid = threadIdx.x;
    const int lane = tid & 31;
    const int g = lane >> 2;
    const int tig = lane & 3;
    const int w = tid >> 5;
    const int wm = w >> 2;
    const int wn = w & 3;
    const int row0 = blockIdx.x * 64;

    const int a_row = tid >> 3;
    const int a_c4  = tid & 7;
    const int b_row = tid >> 1;
    const int b_c4  = (tid & 1) * 4;

    float c[2][4][4];
#pragma unroll
    for (int mt = 0; mt < 2; mt++)
#pragma unroll
        for (int nt = 0; nt < 4; nt++)
#pragma unroll
            for (int r = 0; r < 4; r++) c[mt][nt][r] = 0.f;

    // ================= Stage A =================
#pragma unroll
    for (int ch = 0; ch < 4; ch++) {
        const int kb = ch * 32;
        float4 ra[2], rb[4];
#pragma unroll
        for (int p = 0; p < 2; p++) {
            int gm = row0 + a_row + p * 32;
            float4 v = make_float4(0.f, 0.f, 0.f, 0.f);
            if (gm < M)
                v = *reinterpret_cast<const float4*>(g_emean + (size_t)gm * CC + kb + a_c4 * 4);
            ra[p] = v;
        }
#pragma unroll
        for (int p = 0; p < 4; p++)
            rb[p] = *reinterpret_cast<const float4*>(W1 + (size_t)b_row * CC + kb + (b_c4 + p) * 4);
        if (ch > 0) __syncthreads();
#pragma unroll
        for (int p = 0; p < 2; p++) {
            int r = a_row + p * 32;
            As[r][a_c4 * 4 + 0] = f2tf32(ra[p].x);
            As[r][a_c4 * 4 + 1] = f2tf32(ra[p].y);
            As[r][a_c4 * 4 + 2] = f2tf32(ra[p].z);
            As[r][a_c4 * 4 + 3] = f2tf32(ra[p].w);
        }
#pragma unroll
        for (int p = 0; p < 4; p++) {
            int kcol = (b_c4 + p) * 4;
            Bs[b_row][kcol + 0] = f2tf32(rb[p].x);
            Bs[b_row][kcol + 1] = f2tf32(rb[p].y);
            Bs[b_row][kcol + 2] = f2tf32(rb[p].z);
            Bs[b_row][kcol + 3] = f2tf32(rb[p].w);
        }
        __syncthreads();
#pragma unroll
        for (int ks = 0; ks < 4; ks++) {
            const int k0 = ks * 8;
            uint32_t a[2][4], b[4][2];
#pragma unroll
            for (int mt = 0; mt < 2; mt++) {
                int mb = wm * 32 + mt * 16;
                a[mt][0] = As[mb + g][k0 + tig];
                a[mt][1] = As[mb + g + 8][k0 + tig];
                a[mt][2] = As[mb + g][k0 + tig + 4];
                a[mt][3] = As[mb + g + 8][k0 + tig + 4];
            }
#pragma unroll
            for (int nt = 0; nt < 4; nt++) {
                int nb = wn * 32 + nt * 8;
                b[nt][0] = Bs[nb + g][k0 + tig];
                b[nt][1] = Bs[nb + g][k0 + tig + 4];
            }
#pragma unroll
            for (int mt = 0; mt < 2; mt++)
#pragma unroll
                for (int nt = 0; nt < 4; nt++)
                    asm volatile(
                        "mma.sync.aligned.m16n8k8.row.col.f32.tf32.tf32.f32 "
                        "{%0,%1,%2,%3}, {%4,%5,%6,%7}, {%8,%9}, {%0,%1,%2,%3};"
                        : "+f"(c[mt][nt][0]), "+f"(c[mt][nt][1]),
                          "+f"(c[mt][nt][2]), "+f"(c[mt][nt][3])
                        : "r"(a[mt][0]), "r"(a[mt][1]), "r"(a[mt][2]), "r"(a[mt][3]),
                          "r"(b[nt][0]), "r"(b[nt][1]));
        }
    }
    __syncthreads();

    // ---- T = relu(c + b1) -> Ts (tf32); reset accumulators ----
#pragma unroll
    for (int nt = 0; nt < 4; nt++) {
        int col = wn * 32 + nt * 8 + tig * 2;
        float bb0 = __ldg(b1 + col);
        float bb1 = __ldg(b1 + col + 1);
#pragma unroll
        for (int mt = 0; mt < 2; mt++) {
            int mb = wm * 32 + mt * 16;
            Ts[mb + g][col]         = f2tf32(fmaxf(c[mt][nt][0] + bb0, 0.f));
            Ts[mb + g][col + 1]     = f2tf32(fmaxf(c[mt][nt][1] + bb1, 0.f));
            Ts[mb + g + 8][col]     = f2tf32(fmaxf(c[mt][nt][2] + bb0, 0.f));
            Ts[mb + g + 8][col + 1] = f2tf32(fmaxf(c[mt][nt][3] + bb1, 0.f));
            c[mt][nt][0] = 0.f; c[mt][nt][1] = 0.f;
            c[mt][nt][2] = 0.f; c[mt][nt][3] = 0.f;
        }
    }

    // ================= Stage B =================
#pragma unroll
    for (int ch = 0; ch < 4; ch++) {
        const int kb = ch * 32;
        float4 rb[4];
#pragma unroll
        for (int p = 0; p < 4; p++)
            rb[p] = *reinterpret_cast<const float4*>(W2 + (size_t)b_row * CC + kb + (b_c4 + p) * 4);
        __syncthreads();
#pragma unroll
        for (int p = 0; p < 4; p++) {
            int kcol = (b_c4 + p) * 4;
            Bs[b_row][kcol + 0] = f2tf32(rb[p].x);
            Bs[b_row][kcol + 1] = f2tf32(rb[p].y);
            Bs[b_row][kcol + 2] = f2tf32(rb[p].z);
            Bs[b_row][kcol + 3] = f2tf32(rb[p].w);
        }
        __syncthreads();
#pragma unroll
        for (int ks = 0; ks < 4; ks++) {
            const int k0 = ks * 8;
            const int kk = kb + k0;
            uint32_t a[2][4], b[4][2];
#pragma unroll
            for (int mt = 0; mt < 2; mt++) {
                int mb = wm * 32 + mt * 16;
                a[mt][0] = Ts[mb + g][kk + tig];
                a[mt][1] = Ts[mb + g + 8][kk + tig];
                a[mt][2] = Ts[mb + g][kk + tig + 4];
                a[mt][3] = Ts[mb + g + 8][kk + tig + 4];
            }
#pragma unroll
            for (int nt = 0; nt < 4; nt++) {
                int nb = wn * 32 + nt * 8;
                b[nt][0] = Bs[nb + g][k0 + tig];
                b[nt][1] = Bs[nb + g][k0 + tig + 4];
            }
#pragma unroll
            for (int mt = 0; mt < 2; mt++)
#pragma unroll
                for (int nt = 0; nt < 4; nt++)
                    asm volatile(
                        "mma.sync.aligned.m16n8k8.row.col.f32.tf32.tf32.f32 "
                        "{%0,%1,%2,%3}, {%4,%5,%6,%7}, {%8,%9}, {%0,%1,%2,%3};"
                        : "+f"(c[mt][nt][0]), "+f"(c[mt][nt][1]),
                          "+f"(c[mt][nt][2]), "+f"(c[mt][nt][3])
                        : "r"(a[mt][0]), "r"(a[mt][1]), "r"(a[mt][2]), "r"(a[mt][3]),
                          "r"(b[nt][0]), "r"(b[nt][1]));
        }
    }

    // ---- epilogue: e2 = c + b2 ----
#pragma unroll
    for (int nt = 0; nt < 4; nt++) {
        int col = wn * 32 + nt * 8 + tig * 2;
        float bb0 = __ldg(b2 + col);
        float bb1 = __ldg(b2 + col + 1);
#pragma unroll
        for (int mt = 0; mt < 2; mt++) {
            int mb = row0 + wm * 32 + mt * 16;
            int r0 = mb + g;
            int r1 = mb + g + 8;
            if (r0 < M)
                *reinterpret_cast<float2*>(g_e2 + (size_t)r0 * CC + col) =
                    make_float2(c[mt][nt][0] + bb0, c[mt][nt][1] + bb1);
            if (r1 < M)
                *reinterpret_cast<float2*>(g_e2 + (size_t)r1 * CC + col) =
                    make_float2(c[mt][nt][2] + bb0, c[mt][nt][3] + bb1);
        }
    }
}

extern "C" void kernel_launch(void* const* d_in, const int* in_sizes, int n_in,
                              void* d_out, int out_size) {
    const float* x  = (const float*)d_in[0];
    const int*   hi = (const int*)d_in[1];
    const float* W1 = (const float*)d_in[2];
    const float* b1 = (const float*)d_in[3];
    const float* W2 = (const float*)d_in[4];
    const float* b2 = (const float*)d_in[5];
    float* out = (float*)d_out;

    int ninc = in_sizes[1] / 2;
    const int* nidx = hi;          // hyperedge_index[0]
    const int* eidx = hi + ninc;   // hyperedge_index[1]

    constexpr int SMEM_BYTES = (64 * 132 + 128 * 36 + 64 * 36) * 4;  // 61440
    static int attr_set = 0;
    if (!attr_set) {
        cudaFuncSetAttribute(fused_gemm, cudaFuncAttributeMaxDynamicSharedMemorySize,
                             SMEM_BYTES);
        attr_set = 1;
    }

    int qthreads = (ninc + 3) / 4;
    prep_kernel<<<296, 256>>>();
    fill_kernel<<<(qthreads + 255) / 256, 256>>>(nidx, eidx, ninc);
    gather1_kernel<<<(NE * 32 + 255) / 256, 256>>>(x);
    fused_gemm<<<(NE + 63) / 64, 256, SMEM_BYTES>>>(W1, b1, W2, b2);
    gather2_kernel<<<(NN * 32 + 255) / 256, 256>>>(out);
}

// round 15
// speedup vs baseline: 1.2421x; 1.2421x over previous
#include <cuda_runtime.h>
#include <cstdint>

#define NN 50000
#define NE 25000
#define CC 128
#define MAXINC 700000
#define UQ 8   // incidences per thread in count/fill

// ---- scratch (device globals; no allocation) ----
__device__ __align__(16) float g_emean[NE * CC];  // per-edge mean of gathered x
__device__ __align__(16) float g_e2[NE * CC];     // (relu(mean@W1^T+b1))@W2^T + b2
__device__ int g_cc_e[NE];      // per-edge degree
__device__ int g_cc_n[NN];      // per-node degree
__device__ int g_off_e[NE];     // region start offsets
__device__ int g_off_n[NN];
__device__ int g_pos_e[NE];     // fill cursors
__device__ int g_pos_n[NN];
__device__ int g_cur_e;         // global cursors for offset assignment
__device__ int g_cur_n;
__device__ int g_lst_e[MAXINC]; // node ids grouped by edge
__device__ int g_lst_n[MAXINC]; // edge ids grouped by node

// ---- prep: zero degree counters + cursors ----
__global__ void prep_kernel() {
    int tid = blockIdx.x * blockDim.x + threadIdx.x;
    int stride = gridDim.x * blockDim.x;
    for (int i = tid; i < NE; i += stride) g_cc_e[i] = 0;
    for (int i = tid; i < NN; i += stride) g_cc_n[i] = 0;
    if (tid == 0) { g_cur_e = 0; g_cur_n = 0; }
}

// ---- count: UQ incidences per thread (fire-and-forget REDG) ----
__global__ void count_kernel(const int* __restrict__ nidx,
                             const int* __restrict__ eidx, int ninc) {
    int base = (blockIdx.x * blockDim.x + threadIdx.x) * UQ;
    if (base >= ninc) return;
    int cnt = min(UQ, ninc - base);
#pragma unroll
    for (int q = 0; q < UQ; q++) {
        if (q < cnt) {
            atomicAdd(&g_cc_e[__ldg(eidx + base + q)], 1);
            atomicAdd(&g_cc_n[__ldg(nidx + base + q)], 1);
        }
    }
}

// ---- offsets: block-aggregated atomic-cursor assignment ----
// blocks [0, EB) -> edges, blocks [EB, EB+NB) -> nodes. 1024 threads/block.
#define EB ((NE + 1023) / 1024)
#define NB ((NN + 1023) / 1024)
__global__ void __launch_bounds__(1024) offset_kernel() {
    bool is_node = blockIdx.x >= EB;
    const int* cc = is_node ? g_cc_n : g_cc_e;
    int* off = is_node ? g_off_n : g_off_e;
    int* pos = is_node ? g_pos_n : g_pos_e;
    int* cur = is_node ? &g_cur_n : &g_cur_e;
    int n = is_node ? NN : NE;
    int blk = is_node ? (blockIdx.x - EB) : blockIdx.x;

    __shared__ int warp_sums[32];
    __shared__ int s_base;
    int tid = threadIdx.x, lane = tid & 31, wid = tid >> 5;
    int i = blk * 1024 + tid;
    int v = (i < n) ? cc[i] : 0;
    int s = v;
#pragma unroll
    for (int d = 1; d < 32; d <<= 1) {
        int t = __shfl_up_sync(0xffffffffu, s, d);
        if (lane >= d) s += t;
    }
    if (lane == 31) warp_sums[wid] = s;
    __syncthreads();
    if (wid == 0) {
        int ws = warp_sums[lane];
#pragma unroll
        for (int d = 1; d < 32; d <<= 1) {
            int t = __shfl_up_sync(0xffffffffu, ws, d);
            if (lane >= d) ws += t;
        }
        warp_sums[lane] = ws;
        if (lane == 31) s_base = atomicAdd(cur, ws);
    }
    __syncthreads();
    int excl = s - v + (wid ? warp_sums[wid - 1] : 0) + s_base;
    if (i < n) { off[i] = excl; pos[i] = excl; }
}

// ---- fill: UQ incidences per thread, independent atomic chains ----
__global__ void fill_kernel(const int* __restrict__ nidx,
                            const int* __restrict__ eidx, int ninc) {
    int base = (blockIdx.x * blockDim.x + threadIdx.x) * UQ;
    if (base >= ninc) return;
    int cnt = min(UQ, ninc - base);
    int n[UQ], e[UQ];
#pragma unroll
    for (int q = 0; q < UQ; q++) {
        int i = (q < cnt) ? base + q : base;
        n[q] = __ldg(nidx + i);
        e[q] = __ldg(eidx + i);
    }
    int p[UQ], r[UQ];
#pragma unroll
    for (int q = 0; q < UQ; q++) {
        if (q < cnt) {
            p[q] = atomicAdd(&g_pos_e[e[q]], 1);
            r[q] = atomicAdd(&g_pos_n[n[q]], 1);
        }
    }
#pragma unroll
    for (int q = 0; q < UQ; q++) {
        if (q < cnt) {
            g_lst_e[p[q]] = n[q];
            g_lst_n[r[q]] = e[q];
        }
    }
}

// ---- gather1: g_emean[e] = mean of x[n] over incident nodes ----
__global__ void gather1_kernel(const float* __restrict__ x) {
    int gw = (blockIdx.x * blockDim.x + threadIdx.x) >> 5;
    int lane = threadIdx.x & 31;
    if (gw >= NE) return;
    int off = __ldg(g_off_e + gw);
    int deg = __ldg(g_cc_e + gw);
    float4 acc = make_float4(0.f, 0.f, 0.f, 0.f);
    int j = 0;
    for (; j + 4 <= deg; j += 4) {
        int n0 = __ldg(g_lst_e + off + j);
        int n1 = __ldg(g_lst_e + off + j + 1);
        int n2 = __ldg(g_lst_e + off + j + 2);
        int n3 = __ldg(g_lst_e + off + j + 3);
        float4 v0 = *reinterpret_cast<const float4*>(x + (size_t)n0 * CC + lane * 4);
        float4 v1 = *reinterpret_cast<const float4*>(x + (size_t)n1 * CC + lane * 4);
        float4 v2 = *reinterpret_cast<const float4*>(x + (size_t)n2 * CC + lane * 4);
        float4 v3 = *reinterpret_cast<const float4*>(x + (size_t)n3 * CC + lane * 4);
        acc.x += v0.x + v1.x + v2.x + v3.x;
        acc.y += v0.y + v1.y + v2.y + v3.y;
        acc.z += v0.z + v1.z + v2.z + v3.z;
        acc.w += v0.w + v1.w + v2.w + v3.w;
    }
    for (; j < deg; j++) {
        int n0 = __ldg(g_lst_e + off + j);
        float4 v0 = *reinterpret_cast<const float4*>(x + (size_t)n0 * CC + lane * 4);
        acc.x += v0.x; acc.y += v0.y; acc.z += v0.z; acc.w += v0.w;
    }
    float s = 1.f / (float)max(deg, 1);
    acc.x *= s; acc.y *= s; acc.z *= s; acc.w *= s;
    *reinterpret_cast<float4*>(g_emean + (size_t)gw * CC + lane * 4) = acc;
}

// ---- gather2: out[n] = relu(mean of g_e2[e] over incident edges) ----
__global__ void gather2_kernel(float* __restrict__ out) {
    int gw = (blockIdx.x * blockDim.x + threadIdx.x) >> 5;
    int lane = threadIdx.x & 31;
    if (gw >= NN) return;
    int off = __ldg(g_off_n + gw);
    int deg = __ldg(g_cc_n + gw);
    float4 acc = make_float4(0.f, 0.f, 0.f, 0.f);
    int j = 0;
    for (; j + 4 <= deg; j += 4) {
        int e0 = __ldg(g_lst_n + off + j);
        int e1 = __ldg(g_lst_n + off + j + 1);
        int e2i = __ldg(g_lst_n + off + j + 2);
        int e3 = __ldg(g_lst_n + off + j + 3);
        float4 v0 = *reinterpret_cast<const float4*>(g_e2 + (size_t)e0 * CC + lane * 4);
        float4 v1 = *reinterpret_cast<const float4*>(g_e2 + (size_t)e1 * CC + lane * 4);
        float4 v2 = *reinterpret_cast<const float4*>(g_e2 + (size_t)e2i * CC + lane * 4);
        float4 v3 = *reinterpret_cast<const float4*>(g_e2 + (size_t)e3 * CC + lane * 4);
        acc.x += v0.x + v1.x + v2.x + v3.x;
        acc.y += v0.y + v1.y + v2.y + v3.y;
        acc.z += v0.z + v1.z + v2.z + v3.z;
        acc.w += v0.w + v1.w + v2.w + v3.w;
    }
    for (; j < deg; j++) {
        int e0 = __ldg(g_lst_n + off + j);
        float4 v0 = *reinterpret_cast<const float4*>(g_e2 + (size_t)e0 * CC + lane * 4);
        acc.x += v0.x; acc.y += v0.y; acc.z += v0.z; acc.w += v0.w;
    }
    float s = 1.f / (float)max(deg, 1);
    acc.x = fmaxf(acc.x * s, 0.f);
    acc.y = fmaxf(acc.y * s, 0.f);
    acc.z = fmaxf(acc.z * s, 0.f);
    acc.w = fmaxf(acc.w * s, 0.f);
    *reinterpret_cast<float4*>(out + (size_t)gw * CC + lane * 4) = acc;
}

__device__ __forceinline__ uint32_t f2tf32(float f) {
    uint32_t u;
    asm("cvt.rna.tf32.f32 %0, %1;" : "=r"(u) : "f"(f));
    return u;
}

// ---- fused double tf32 GEMM per 64-row tile ----
// Stage A: T = relu( g_emean @ W1^T + b1 )  [64x128], kept in smem (tf32)
// Stage B: e2 = T @ W2^T + b2               [64x128], written to gmem
__global__ void __launch_bounds__(256) fused_gemm(const float* __restrict__ W1,
                                                  const float* __restrict__ b1,
                                                  const float* __restrict__ W2,
                                                  const float* __restrict__ b2) {
    extern __shared__ uint32_t smem[];
    uint32_t (*Ts)[132] = reinterpret_cast<uint32_t(*)[132]>(smem);
    uint32_t (*Bs)[36]  = reinterpret_cast<uint32_t(*)[36]>(smem + 64 * 132);
    uint32_t (*As)[36]  = reinterpret_cast<uint32_t(*)[36]>(smem + 64 * 132 + 128 * 36);

    const int M = NE;
    const int tid = threadIdx.x;
    const int lane = tid & 31;
    const int g = lane >> 2;
    const int tig = lane & 3;
    const int w = tid >> 5;
    const int wm = w >> 2;
    const int wn = w & 3;
    const int row0 = blockIdx.x * 64;

    const int a_row = tid >> 3;
    const int a_c4  = tid & 7;
    const int b_row = tid >> 1;
    const int b_c4  = (tid & 1) * 4;

    float c[2][4][4];
#pragma unroll
    for (int mt = 0; mt < 2; mt++)
#pragma unroll
        for (int nt = 0; nt < 4; nt++)
#pragma unroll
            for (int r = 0; r < 4; r++) c[mt][nt][r] = 0.f;

    // ================= Stage A =================
#pragma unroll
    for (int ch = 0; ch < 4; ch++) {
        const int kb = ch * 32;
        float4 ra[2], rb[4];
#pragma unroll
        for (int p = 0; p < 2; p++) {
            int gm = row0 + a_row + p * 32;
            float4 v = make_float4(0.f, 0.f, 0.f, 0.f);
            if (gm < M)
                v = *reinterpret_cast<const float4*>(g_emean + (size_t)gm * CC + kb + a_c4 * 4);
            ra[p] = v;
        }
#pragma unroll
        for (int p = 0; p < 4; p++)
            rb[p] = *reinterpret_cast<const float4*>(W1 + (size_t)b_row * CC + kb + (b_c4 + p) * 4);
        if (ch > 0) __syncthreads();
#pragma unroll
        for (int p = 0; p < 2; p++) {
            int r = a_row + p * 32;
            As[r][a_c4 * 4 + 0] = f2tf32(ra[p].x);
            As[r][a_c4 * 4 + 1] = f2tf32(ra[p].y);
            As[r][a_c4 * 4 + 2] = f2tf32(ra[p].z);
            As[r][a_c4 * 4 + 3] = f2tf32(ra[p].w);
        }
#pragma unroll
        for (int p = 0; p < 4; p++) {
            int kcol = (b_c4 + p) * 4;
            Bs[b_row][kcol + 0] = f2tf32(rb[p].x);
            Bs[b_row][kcol + 1] = f2tf32(rb[p].y);
            Bs[b_row][kcol + 2] = f2tf32(rb[p].z);
            Bs[b_row][kcol + 3] = f2tf32(rb[p].w);
        }
        __syncthreads();
#pragma unroll
        for (int ks = 0; ks < 4; ks++) {
            const int k0 = ks * 8;
            uint32_t a[2][4], b[4][2];
#pragma unroll
            for (int mt = 0; mt < 2; mt++) {
                int mb = wm * 32 + mt * 16;
                a[mt][0] = As[mb + g][k0 + tig];
                a[mt][1] = As[mb + g + 8][k0 + tig];
                a[mt][2] = As[mb + g][k0 + tig + 4];
                a[mt][3] = As[mb + g + 8][k0 + tig + 4];
            }
#pragma unroll
            for (int nt = 0; nt < 4; nt++) {
                int nb = wn * 32 + nt * 8;
                b[nt][0] = Bs[nb + g][k0 + tig];
                b[nt][1] = Bs[nb + g][k0 + tig + 4];
            }
#pragma unroll
            for (int mt = 0; mt < 2; mt++)
#pragma unroll
                for (int nt = 0; nt < 4; nt++)
                    asm volatile(
                        "mma.sync.aligned.m16n8k8.row.col.f32.tf32.tf32.f32 "
                        "{%0,%1,%2,%3}, {%4,%5,%6,%7}, {%8,%9}, {%0,%1,%2,%3};"
                        : "+f"(c[mt][nt][0]), "+f"(c[mt][nt][1]),
                          "+f"(c[mt][nt][2]), "+f"(c[mt][nt][3])
                        : "r"(a[mt][0]), "r"(a[mt][1]), "r"(a[mt][2]), "r"(a[mt][3]),
                          "r"(b[nt][0]), "r"(b[nt][1]));
        }
    }
    __syncthreads();

    // ---- T = relu(c + b1) -> Ts (tf32); reset accumulators ----
#pragma unroll
    for (int nt = 0; nt < 4; nt++) {
        int col = wn * 32 + nt * 8 + tig * 2;
        float bb0 = __ldg(b1 + col);
        float bb1 = __ldg(b1 + col + 1);
#pragma unroll
        for (int mt = 0; mt < 2; mt++) {
            int mb = wm * 32 + mt * 16;
            Ts[mb + g][col]         = f2tf32(fmaxf(c[mt][nt][0] + bb0, 0.f));
            Ts[mb + g][col + 1]     = f2tf32(fmaxf(c[mt][nt][1] + bb1, 0.f));
            Ts[mb + g + 8][col]     = f2tf32(fmaxf(c[mt][nt][2] + bb0, 0.f));
            Ts[mb + g + 8][col + 1] = f2tf32(fmaxf(c[mt][nt][3] + bb1, 0.f));
            c[mt][nt][0] = 0.f; c[mt][nt][1] = 0.f;
            c[mt][nt][2] = 0.f; c[mt][nt][3] = 0.f;
        }
    }

    // ================= Stage B =================
#pragma unroll
    for (int ch = 0; ch < 4; ch++) {
        const int kb = ch * 32;
        float4 rb[4];
#pragma unroll
        for (int p = 0; p < 4; p++)
            rb[p] = *reinterpret_cast<const float4*>(W2 + (size_t)b_row * CC + kb + (b_c4 + p) * 4);
        __syncthreads();
#pragma unroll
        for (int p = 0; p < 4; p++) {
            int kcol = (b_c4 + p) * 4;
            Bs[b_row][kcol + 0] = f2tf32(rb[p].x);
            Bs[b_row][kcol + 1] = f2tf32(rb[p].y);
            Bs[b_row][kcol + 2] = f2tf32(rb[p].z);
            Bs[b_row][kcol + 3] = f2tf32(rb[p].w);
        }
        __syncthreads();
#pragma unroll
        for (int ks = 0; ks < 4; ks++) {
            const int k0 = ks * 8;
            const int kk = kb + k0;
            uint32_t a[2][4], b[4][2];
#pragma unroll
            for (int mt = 0; mt < 2; mt++) {
                int mb = wm * 32 + mt * 16;
                a[mt][0] = Ts[mb + g][kk + tig];
                a[mt][1] = Ts[mb + g + 8][kk + tig];
                a[mt][2] = Ts[mb + g][kk + tig + 4];
                a[mt][3] = Ts[mb + g + 8][kk + tig + 4];
            }
#pragma unroll
            for (int nt = 0; nt < 4; nt++) {
                int nb = wn * 32 + nt * 8;
                b[nt][0] = Bs[nb + g][k0 + tig];
                b[nt][1] = Bs[nb + g][k0 + tig + 4];
            }
#pragma unroll
            for (int mt = 0; mt < 2; mt++)
#pragma unroll
                for (int nt = 0; nt < 4; nt++)
                    asm volatile(
                        "mma.sync.aligned.m16n8k8.row.col.f32.tf32.tf32.f32 "
                        "{%0,%1,%2,%3}, {%4,%5,%6,%7}, {%8,%9}, {%0,%1,%2,%3};"
                        : "+f"(c[mt][nt][0]), "+f"(c[mt][nt][1]),
                          "+f"(c[mt][nt][2]), "+f"(c[mt][nt][3])
                        : "r"(a[mt][0]), "r"(a[mt][1]), "r"(a[mt][2]), "r"(a[mt][3]),
                          "r"(b[nt][0]), "r"(b[nt][1]));
        }
    }

    // ---- epilogue: e2 = c + b2 ----
#pragma unroll
    for (int nt = 0; nt < 4; nt++) {
        int col = wn * 32 + nt * 8 + tig * 2;
        float bb0 = __ldg(b2 + col);
        float bb1 = __ldg(b2 + col + 1);
#pragma unroll
        for (int mt = 0; mt < 2; mt++) {
            int mb = row0 + wm * 32 + mt * 16;
            int r0 = mb + g;
            int r1 = mb + g + 8;
            if (r0 < M)
                *reinterpret_cast<float2*>(g_e2 + (size_t)r0 * CC + col) =
                    make_float2(c[mt][nt][0] + bb0, c[mt][nt][1] + bb1);
            if (r1 < M)
                *reinterpret_cast<float2*>(g_e2 + (size_t)r1 * CC + col) =
                    make_float2(c[mt][nt][2] + bb0, c[mt][nt][3] + bb1);
        }
    }
}

extern "C" void kernel_launch(void* const* d_in, const int* in_sizes, int n_in,
                              void* d_out, int out_size) {
    const float* x  = (const float*)d_in[0];
    const int*   hi = (const int*)d_in[1];
    const float* W1 = (const float*)d_in[2];
    const float* b1 = (const float*)d_in[3];
    const float* W2 = (const float*)d_in[4];
    const float* b2 = (const float*)d_in[5];
    float* out = (float*)d_out;

    int ninc = in_sizes[1] / 2;
    const int* nidx = hi;          // hyperedge_index[0]
    const int* eidx = hi + ninc;   // hyperedge_index[1]

    constexpr int SMEM_BYTES = (64 * 132 + 128 * 36 + 64 * 36) * 4;  // 61440
    static int attr_set = 0;
    if (!attr_set) {
        cudaFuncSetAttribute(fused_gemm, cudaFuncAttributeMaxDynamicSharedMemorySize,
                             SMEM_BYTES);
        attr_set = 1;
    }

    int qthreads = (ninc + UQ - 1) / UQ;
    prep_kernel<<<512, 256>>>();
    count_kernel<<<(qthreads + 255) / 256, 256>>>(nidx, eidx, ninc);
    offset_kernel<<<EB + NB, 1024>>>();
    fill_kernel<<<(qthreads + 255) / 256, 256>>>(nidx, eidx, ninc);
    gather1_kernel<<<(NE * 32 + 255) / 256, 256>>>(x);
    fused_gemm<<<(NE + 63) / 64, 256, SMEM_BYTES>>>(W1, b1, W2, b2);
    gather2_kernel<<<(NN * 32 + 255) / 256, 256>>>(out);
}

// round 16
// speedup vs baseline: 1.2675x; 1.0204x over previous
#include <cuda_runtime.h>
#include <cstdint>

#define NN 50000
#define NE 25000
#define CC 128
#define MAXINC 700000
#define UQ 4   // incidences per thread in count/fill

// ---- scratch (device globals; no allocation) ----
__device__ __align__(16) float g_emean[NE * CC];  // per-edge mean of gathered x
__device__ __align__(16) float g_e2[NE * CC];     // (relu(mean@W1^T+b1))@W2^T + b2
__device__ int g_cc_e[NE];      // per-edge degree
__device__ int g_cc_n[NN];      // per-node degree
__device__ int g_off_e[NE];     // region start offsets
__device__ int g_off_n[NN];
__device__ int g_pos_e[NE];     // fill cursors
__device__ int g_pos_n[NN];
__device__ int g_cur_e;         // global cursors for offset assignment
__device__ int g_cur_n;
__device__ int g_lst_e[MAXINC]; // node ids grouped by edge
__device__ int g_lst_n[MAXINC]; // edge ids grouped by node

// ---- prep: zero degree counters + cursors ----
__global__ void prep_kernel() {
    int tid = blockIdx.x * blockDim.x + threadIdx.x;
    int stride = gridDim.x * blockDim.x;
    for (int i = tid; i < NE; i += stride) g_cc_e[i] = 0;
    for (int i = tid; i < NN; i += stride) g_cc_n[i] = 0;
    if (tid == 0) { g_cur_e = 0; g_cur_n = 0; }
}

// ---- count (edge side): UQ incidences per thread ----
__global__ void count_e_kernel(const int* __restrict__ eidx, int ninc) {
    int base = (blockIdx.x * blockDim.x + threadIdx.x) * UQ;
    if (base >= ninc) return;
    int cnt = min(UQ, ninc - base);
#pragma unroll
    for (int q = 0; q < UQ; q++)
        if (q < cnt) atomicAdd(&g_cc_e[__ldg(eidx + base + q)], 1);
}

// ---- count (node side) ----
__global__ void count_n_kernel(const int* __restrict__ nidx, int ninc) {
    int base = (blockIdx.x * blockDim.x + threadIdx.x) * UQ;
    if (base >= ninc) return;
    int cnt = min(UQ, ninc - base);
#pragma unroll
    for (int q = 0; q < UQ; q++)
        if (q < cnt) atomicAdd(&g_cc_n[__ldg(nidx + base + q)], 1);
}

// ---- offsets: block-aggregated atomic-cursor assignment (per side) ----
#define EB ((NE + 1023) / 1024)
#define NB ((NN + 1023) / 1024)
template <int IS_NODE>
__global__ void __launch_bounds__(1024) offset_kernel() {
    const int* cc = IS_NODE ? g_cc_n : g_cc_e;
    int* off = IS_NODE ? g_off_n : g_off_e;
    int* pos = IS_NODE ? g_pos_n : g_pos_e;
    int* cur = IS_NODE ? &g_cur_n : &g_cur_e;
    const int n = IS_NODE ? NN : NE;

    __shared__ int warp_sums[32];
    __shared__ int s_base;
    int tid = threadIdx.x, lane = tid & 31, wid = tid >> 5;
    int i = blockIdx.x * 1024 + tid;
    int v = (i < n) ? cc[i] : 0;
    int s = v;
#pragma unroll
    for (int d = 1; d < 32; d <<= 1) {
        int t = __shfl_up_sync(0xffffffffu, s, d);
        if (lane >= d) s += t;
    }
    if (lane == 31) warp_sums[wid] = s;
    __syncthreads();
    if (wid == 0) {
        int ws = warp_sums[lane];
#pragma unroll
        for (int d = 1; d < 32; d <<= 1) {
            int t = __shfl_up_sync(0xffffffffu, ws, d);
            if (lane >= d) ws += t;
        }
        warp_sums[lane] = ws;
        if (lane == 31) s_base = atomicAdd(cur, ws);
    }
    __syncthreads();
    int excl = s - v + (wid ? warp_sums[wid - 1] : 0) + s_base;
    if (i < n) { off[i] = excl; pos[i] = excl; }
}

// ---- fill (edge side): list of node ids grouped by edge ----
__global__ void fill_e_kernel(const int* __restrict__ nidx,
                              const int* __restrict__ eidx, int ninc) {
    int base = (blockIdx.x * blockDim.x + threadIdx.x) * UQ;
    if (base >= ninc) return;
    int cnt = min(UQ, ninc - base);
    int n[UQ], e[UQ];
#pragma unroll
    for (int q = 0; q < UQ; q++) {
        int i = (q < cnt) ? base + q : base;
        n[q] = __ldg(nidx + i);
        e[q] = __ldg(eidx + i);
    }
    int p[UQ];
#pragma unroll
    for (int q = 0; q < UQ; q++)
        if (q < cnt) p[q] = atomicAdd(&g_pos_e[e[q]], 1);
#pragma unroll
    for (int q = 0; q < UQ; q++)
        if (q < cnt) g_lst_e[p[q]] = n[q];
}

// ---- fill (node side): list of edge ids grouped by node ----
__global__ void fill_n_kernel(const int* __restrict__ nidx,
                              const int* __restrict__ eidx, int ninc) {
    int base = (blockIdx.x * blockDim.x + threadIdx.x) * UQ;
    if (base >= ninc) return;
    int cnt = min(UQ, ninc - base);
    int n[UQ], e[UQ];
#pragma unroll
    for (int q = 0; q < UQ; q++) {
        int i = (q < cnt) ? base + q : base;
        n[q] = __ldg(nidx + i);
        e[q] = __ldg(eidx + i);
    }
    int r[UQ];
#pragma unroll
    for (int q = 0; q < UQ; q++)
        if (q < cnt) r[q] = atomicAdd(&g_pos_n[n[q]], 1);
#pragma unroll
    for (int q = 0; q < UQ; q++)
        if (q < cnt) g_lst_n[r[q]] = e[q];
}

// ---- gather1: g_emean[e] = mean of x[n] over incident nodes ----
__global__ void gather1_kernel(const float* __restrict__ x) {
    int gw = (blockIdx.x * blockDim.x + threadIdx.x) >> 5;
    int lane = threadIdx.x & 31;
    if (gw >= NE) return;
    int off = __ldg(g_off_e + gw);
    int deg = __ldg(g_cc_e + gw);
    float4 acc = make_float4(0.f, 0.f, 0.f, 0.f);
    int j = 0;
    for (; j + 4 <= deg; j += 4) {
        int n0 = __ldg(g_lst_e + off + j);
        int n1 = __ldg(g_lst_e + off + j + 1);
        int n2 = __ldg(g_lst_e + off + j + 2);
        int n3 = __ldg(g_lst_e + off + j + 3);
        float4 v0 = *reinterpret_cast<const float4*>(x + (size_t)n0 * CC + lane * 4);
        float4 v1 = *reinterpret_cast<const float4*>(x + (size_t)n1 * CC + lane * 4);
        float4 v2 = *reinterpret_cast<const float4*>(x + (size_t)n2 * CC + lane * 4);
        float4 v3 = *reinterpret_cast<const float4*>(x + (size_t)n3 * CC + lane * 4);
        acc.x += v0.x + v1.x + v2.x + v3.x;
        acc.y += v0.y + v1.y + v2.y + v3.y;
        acc.z += v0.z + v1.z + v2.z + v3.z;
        acc.w += v0.w + v1.w + v2.w + v3.w;
    }
    for (; j < deg; j++) {
        int n0 = __ldg(g_lst_e + off + j);
        float4 v0 = *reinterpret_cast<const float4*>(x + (size_t)n0 * CC + lane * 4);
        acc.x += v0.x; acc.y += v0.y; acc.z += v0.z; acc.w += v0.w;
    }
    float s = 1.f / (float)max(deg, 1);
    acc.x *= s; acc.y *= s; acc.z *= s; acc.w *= s;
    *reinterpret_cast<float4*>(g_emean + (size_t)gw * CC + lane * 4) = acc;
}

// ---- gather2: out[n] = relu(mean of g_e2[e] over incident edges) ----
__global__ void gather2_kernel(float* __restrict__ out) {
    int gw = (blockIdx.x * blockDim.x + threadIdx.x) >> 5;
    int lane = threadIdx.x & 31;
    if (gw >= NN) return;
    int off = __ldg(g_off_n + gw);
    int deg = __ldg(g_cc_n + gw);
    float4 acc = make_float4(0.f, 0.f, 0.f, 0.f);
    int j = 0;
    for (; j + 4 <= deg; j += 4) {
        int e0 = __ldg(g_lst_n + off + j);
        int e1 = __ldg(g_lst_n + off + j + 1);
        int e2i = __ldg(g_lst_n + off + j + 2);
        int e3 = __ldg(g_lst_n + off + j + 3);
        float4 v0 = *reinterpret_cast<const float4*>(g_e2 + (size_t)e0 * CC + lane * 4);
        float4 v1 = *reinterpret_cast<const float4*>(g_e2 + (size_t)e1 * CC + lane * 4);
        float4 v2 = *reinterpret_cast<const float4*>(g_e2 + (size_t)e2i * CC + lane * 4);
        float4 v3 = *reinterpret_cast<const float4*>(g_e2 + (size_t)e3 * CC + lane * 4);
        acc.x += v0.x + v1.x + v2.x + v3.x;
        acc.y += v0.y + v1.y + v2.y + v3.y;
        acc.z += v0.z + v1.z + v2.z + v3.z;
        acc.w += v0.w + v1.w + v2.w + v3.w;
    }
    for (; j < deg; j++) {
        int e0 = __ldg(g_lst_n + off + j);
        float4 v0 = *reinterpret_cast<const float4*>(g_e2 + (size_t)e0 * CC + lane * 4);
        acc.x += v0.x; acc.y += v0.y; acc.z += v0.z; acc.w += v0.w;
    }
    float s = 1.f / (float)max(deg, 1);
    acc.x = fmaxf(acc.x * s, 0.f);
    acc.y = fmaxf(acc.y * s, 0.f);
    acc.z = fmaxf(acc.z * s, 0.f);
    acc.w = fmaxf(acc.w * s, 0.f);
    *reinterpret_cast<float4*>(out + (size_t)gw * CC + lane * 4) = acc;
}

__device__ __forceinline__ uint32_t f2tf32(float f) {
    uint32_t u;
    asm("cvt.rna.tf32.f32 %0, %1;" : "=r"(u) : "f"(f));
    return u;
}

// ---- fused double tf32 GEMM per 64-row tile ----
__global__ void __launch_bounds__(256) fused_gemm(const float* __restrict__ W1,
                                                  const float* __restrict__ b1,
                                                  const float* __restrict__ W2,
                                                  const float* __restrict__ b2) {
    extern __shared__ uint32_t smem[];
    uint32_t (*Ts)[132] = reinterpret_cast<uint32_t(*)[132]>(smem);
    uint32_t (*Bs)[36]  = reinterpret_cast<uint32_t(*)[36]>(smem + 64 * 132);
    uint32_t (*As)[36]  = reinterpret_cast<uint32_t(*)[36]>(smem + 64 * 132 + 128 * 36);

    const int M = NE;
    const int tid = threadIdx.x;
    const int lane = tid & 31;
    const int g = lane >> 2;
    const int tig = lane & 3;
    const int w = tid >> 5;
    const int wm = w >> 2;
    const int wn = w & 3;
    const int row0 = blockIdx.x * 64;

    const int a_row = tid >> 3;
    const int a_c4  = tid & 7;
    const int b_row = tid >> 1;
    const int b_c4  = (tid & 1) * 4;

    float c[2][4][4];
#pragma unroll
    for (int mt = 0; mt < 2; mt++)
#pragma unroll
        for (int nt = 0; nt < 4; nt++)
#pragma unroll
            for (int r = 0; r < 4; r++) c[mt][nt][r] = 0.f;

    // ================= Stage A =================
#pragma unroll
    for (int ch = 0; ch < 4; ch++) {
        const int kb = ch * 32;
        float4 ra[2], rb[4];
#pragma unroll
        for (int p = 0; p < 2; p++) {
            int gm = row0 + a_row + p * 32;
            float4 v = make_float4(0.f, 0.f, 0.f, 0.f);
            if (gm < M)
                v = *reinterpret_cast<const float4*>(g_emean + (size_t)gm * CC + kb + a_c4 * 4);
            ra[p] = v;
        }
#pragma unroll
        for (int p = 0; p < 4; p++)
            rb[p] = *reinterpret_cast<const float4*>(W1 + (size_t)b_row * CC + kb + (b_c4 + p) * 4);
        if (ch > 0) __syncthreads();
#pragma unroll
        for (int p = 0; p < 2; p++) {
            int r = a_row + p * 32;
            As[r][a_c4 * 4 + 0] = f2tf32(ra[p].x);
            As[r][a_c4 * 4 + 1] = f2tf32(ra[p].y);
            As[r][a_c4 * 4 + 2] = f2tf32(ra[p].z);
            As[r][a_c4 * 4 + 3] = f2tf32(ra[p].w);
        }
#pragma unroll
        for (int p = 0; p < 4; p++) {
            int kcol = (b_c4 + p) * 4;
            Bs[b_row][kcol + 0] = f2tf32(rb[p].x);
            Bs[b_row][kcol + 1] = f2tf32(rb[p].y);
            Bs[b_row][kcol + 2] = f2tf32(rb[p].z);
            Bs[b_row][kcol + 3] = f2tf32(rb[p].w);
        }
        __syncthreads();
#pragma unroll
        for (int ks = 0; ks < 4; ks++) {
            const int k0 = ks * 8;
            uint32_t a[2][4], b[4][2];
#pragma unroll
            for (int mt = 0; mt < 2; mt++) {
                int mb = wm * 32 + mt * 16;
                a[mt][0] = As[mb + g][k0 + tig];
                a[mt][1] = As[mb + g + 8][k0 + tig];
                a[mt][2] = As[mb + g][k0 + tig + 4];
                a[mt][3] = As[mb + g + 8][k0 + tig + 4];
            }
#pragma unroll
            for (int nt = 0; nt < 4; nt++) {
                int nb = wn * 32 + nt * 8;
                b[nt][0] = Bs[nb + g][k0 + tig];
                b[nt][1] = Bs[nb + g][k0 + tig + 4];
            }
#pragma unroll
            for (int mt = 0; mt < 2; mt++)
#pragma unroll
                for (int nt = 0; nt < 4; nt++)
                    asm volatile(
                        "mma.sync.aligned.m16n8k8.row.col.f32.tf32.tf32.f32 "
                        "{%0,%1,%2,%3}, {%4,%5,%6,%7}, {%8,%9}, {%0,%1,%2,%3};"
                        : "+f"(c[mt][nt][0]), "+f"(c[mt][nt][1]),
                          "+f"(c[mt][nt][2]), "+f"(c[mt][nt][3])
                        : "r"(a[mt][0]), "r"(a[mt][1]), "r"(a[mt][2]), "r"(a[mt][3]),
                          "r"(b[nt][0]), "r"(b[nt][1]));
        }
    }
    __syncthreads();

    // ---- T = relu(c + b1) -> Ts (tf32); reset accumulators ----
#pragma unroll
    for (int nt = 0; nt < 4; nt++) {
        int col = wn * 32 + nt * 8 + tig * 2;
        float bb0 = __ldg(b1 + col);
        float bb1 = __ldg(b1 + col + 1);
#pragma unroll
        for (int mt = 0; mt < 2; mt++) {
            int mb = wm * 32 + mt * 16;
            Ts[mb + g][col]         = f2tf32(fmaxf(c[mt][nt][0] + bb0, 0.f));
            Ts[mb + g][col + 1]     = f2tf32(fmaxf(c[mt][nt][1] + bb1, 0.f));
            Ts[mb + g + 8][col]     = f2tf32(fmaxf(c[mt][nt][2] + bb0, 0.f));
            Ts[mb + g + 8][col + 1] = f2tf32(fmaxf(c[mt][nt][3] + bb1, 0.f));
            c[mt][nt][0] = 0.f; c[mt][nt][1] = 0.f;
            c[mt][nt][2] = 0.f; c[mt][nt][3] = 0.f;
        }
    }

    // ================= Stage B =================
#pragma unroll
    for (int ch = 0; ch < 4; ch++) {
        const int kb = ch * 32;
        float4 rb[4];
#pragma unroll
        for (int p = 0; p < 4; p++)
            rb[p] = *reinterpret_cast<const float4*>(W2 + (size_t)b_row * CC + kb + (b_c4 + p) * 4);
        __syncthreads();
#pragma unroll
        for (int p = 0; p < 4; p++) {
            int kcol = (b_c4 + p) * 4;
            Bs[b_row][kcol + 0] = f2tf32(rb[p].x);
            Bs[b_row][kcol + 1] = f2tf32(rb[p].y);
            Bs[b_row][kcol + 2] = f2tf32(rb[p].z);
            Bs[b_row][kcol + 3] = f2tf32(rb[p].w);
        }
        __syncthreads();
#pragma unroll
        for (int ks = 0; ks < 4; ks++) {
            const int k0 = ks * 8;
            const int kk = kb + k0;
            uint32_t a[2][4], b[4][2];
#pragma unroll
            for (int mt = 0; mt < 2; mt++) {
                int mb = wm * 32 + mt * 16;
                a[mt][0] = Ts[mb + g][kk + tig];
                a[mt][1] = Ts[mb + g + 8][kk + tig];
                a[mt][2] = Ts[mb + g][kk + tig + 4];
                a[mt][3] = Ts[mb + g + 8][kk + tig + 4];
            }
#pragma unroll
            for (int nt = 0; nt < 4; nt++) {
                int nb = wn * 32 + nt * 8;
                b[nt][0] = Bs[nb + g][k0 + tig];
                b[nt][1] = Bs[nb + g][k0 + tig + 4];
            }
#pragma unroll
            for (int mt = 0; mt < 2; mt++)
#pragma unroll
                for (int nt = 0; nt < 4; nt++)
                    asm volatile(
                        "mma.sync.aligned.m16n8k8.row.col.f32.tf32.tf32.f32 "
                        "{%0,%1,%2,%3}, {%4,%5,%6,%7}, {%8,%9}, {%0,%1,%2,%3};"
                        : "+f"(c[mt][nt][0]), "+f"(c[mt][nt][1]),
                          "+f"(c[mt][nt][2]), "+f"(c[mt][nt][3])
                        : "r"(a[mt][0]), "r"(a[mt][1]), "r"(a[mt][2]), "r"(a[mt][3]),
                          "r"(b[nt][0]), "r"(b[nt][1]));
        }
    }

    // ---- epilogue: e2 = c + b2 ----
#pragma unroll
    for (int nt = 0; nt < 4; nt++) {
        int col = wn * 32 + nt * 8 + tig * 2;
        float bb0 = __ldg(b2 + col);
        float bb1 = __ldg(b2 + col + 1);
#pragma unroll
        for (int mt = 0; mt < 2; mt++) {
            int mb = row0 + wm * 32 + mt * 16;
            int r0 = mb + g;
            int r1 = mb + g + 8;
            if (r0 < M)
                *reinterpret_cast<float2*>(g_e2 + (size_t)r0 * CC + col) =
                    make_float2(c[mt][nt][0] + bb0, c[mt][nt][1] + bb1);
            if (r1 < M)
                *reinterpret_cast<float2*>(g_e2 + (size_t)r1 * CC + col) =
                    make_float2(c[mt][nt][2] + bb0, c[mt][nt][3] + bb1);
        }
    }
}

extern "C" void kernel_launch(void* const* d_in, const int* in_sizes, int n_in,
                              void* d_out, int out_size) {
    const float* x  = (const float*)d_in[0];
    const int*   hi = (const int*)d_in[1];
    const float* W1 = (const float*)d_in[2];
    const float* b1 = (const float*)d_in[3];
    const float* W2 = (const float*)d_in[4];
    const float* b2 = (const float*)d_in[5];
    float* out = (float*)d_out;

    int ninc = in_sizes[1] / 2;
    const int* nidx = hi;          // hyperedge_index[0]
    const int* eidx = hi + ninc;   // hyperedge_index[1]

    constexpr int SMEM_BYTES = (64 * 132 + 128 * 36 + 64 * 36) * 4;  // 61440
    static cudaStream_t s2 = nullptr;
    static cudaEvent_t evFork = nullptr, evJoin = nullptr;
    if (!s2) {
        cudaFuncSetAttribute(fused_gemm, cudaFuncAttributeMaxDynamicSharedMemorySize,
                             SMEM_BYTES);
        cudaStreamCreateWithFlags(&s2, cudaStreamNonBlocking);
        cudaEventCreateWithFlags(&evFork, cudaEventDisableTiming);
        cudaEventCreateWithFlags(&evJoin, cudaEventDisableTiming);
    }

    int qblocks = ((ninc + UQ - 1) / UQ + 255) / 256;

    // main (capture) stream: shared prep, then fork
    prep_kernel<<<512, 256>>>();
    cudaEventRecord(evFork, 0);
    cudaStreamWaitEvent(s2, evFork, 0);

    // side stream: node-side build (consumed only by gather2)
    count_n_kernel<<<qblocks, 256, 0, s2>>>(nidx, ninc);
    offset_kernel<1><<<NB, 1024, 0, s2>>>();
    fill_n_kernel<<<qblocks, 256, 0, s2>>>(nidx, eidx, ninc);
    cudaEventRecord(evJoin, s2);

    // main stream: edge-side build -> gather1 -> fused GEMM
    count_e_kernel<<<qblocks, 256>>>(eidx, ninc);
    offset_kernel<0><<<EB, 1024>>>();
    fill_e_kernel<<<qblocks, 256>>>(nidx, eidx, ninc);
    gather1_kernel<<<(NE * 32 + 255) / 256, 256>>>(x);
    fused_gemm<<<(NE + 63) / 64, 256, SMEM_BYTES>>>(W1, b1, W2, b2);

    // join, then final gather
    cudaStreamWaitEvent(0, evJoin, 0);
    gather2_kernel<<<(NN * 32 + 255) / 256, 256>>>(out);
}